// round 15
// baseline (speedup 1.0000x reference)
#include <cuda_runtime.h>
#include <cuda_bf16.h>
#include <cuda_fp16.h>
#include <cstdint>
#include <math.h>

#define NN 50000
#define EE 800000
#define DD 96
#define HS 128                 // padded row stride (halves) for fp16 node arrays
#define MT 64                  // GEMM tile rows per block
#define AS 104                 // A smem row stride in fp16 elems

// ---------------- scratch (device globals) ----------------
__device__ __half g_y116[NN * HS];              // x @ Wc1 (self path), fp16, padded
__device__ __half g_h16[NN * HS];               // x @ Wc0 (neighbor), fp16, padded
__device__ __half g_xh16[NN * HS];              // layer-1 input, fp16, padded
__device__ int   g_rowptr[NN + 1];
// B fragments for mma.sync m16n8k16 (row.col), fp16:
// [layer][mat][hl: 0=hi,1=lo][kchunk 0..5][ntile 0..11][lane 0..31] -> {b0,b1}
__device__ uint2 g_Bfrag[2][2][2][6][12][32];
__device__ float g_biasA[2 * DD];               // b1 @ W2_top + b2
__device__ float g_biasB[2 * DD];               // b0 @ W2_bot (x in-degree)

static __device__ __forceinline__ unsigned short h16_bits(__half h) {
    __half_raw r = *(__half_raw*)&h;
    return r.x;
}

// ---------------- fused setup: rowptr + combine_w + combine_b ----------------
__global__ void setup_all(const int* __restrict__ edst,
                          const float* __restrict__ W0,
                          const float* __restrict__ W1,
                          const float* __restrict__ W2,
                          const float* __restrict__ b0,
                          const float* __restrict__ b1,
                          const float* __restrict__ b2,
                          int E, int N) {
    const int b = blockIdx.x;
    const int tid = threadIdx.x;
    if (b < 196) {
        int n = b * 256 + tid;
        if (n > N) return;
        int lo = 0, hi = E;
        while (lo < hi) { int mid = (lo + hi) >> 1; if (edst[mid] < n) lo = mid + 1; else hi = mid; }
        g_rowptr[n] = lo;
    } else if (b < 580) {
        if (tid >= DD) return;
        int id = b - 196;                 // 0..383
        int r = id % DD;                  // k index
        int mat = (id / DD) & 1;
        int layer = id / (2 * DD);
        int f = tid;                      // n index
        const float* Wa  = (mat == 0 ? W1 : W0) + layer * DD * DD + r * DD;
        const float* W2p = W2 + layer * 2 * DD * DD + (mat == 0 ? 0 : DD) * DD;
        float acc = 0.f;
#pragma unroll 4
        for (int k = 0; k < DD; k++) acc += Wa[k] * W2p[k * DD + f];
        __half hi = __float2half_rn(acc);
        __half lo = __float2half_rn(acc - __half2float(hi));
        int kc  = r >> 4, rem = r & 15;
        int tig = (rem >> 1) & 3, jhi = rem >> 3, jlo = rem & 1;
        int us  = jhi * 2 + jlo;
        int nt  = f >> 3, gid = f & 7;
        int lane = gid * 4 + tig;
        unsigned short* ph = (unsigned short*)&g_Bfrag[layer][mat][0][kc][nt][lane];
        unsigned short* pl = (unsigned short*)&g_Bfrag[layer][mat][1][kc][nt][lane];
        ph[us] = h16_bits(hi);
        pl[us] = h16_bits(lo);
    } else {
        if (tid >= DD) return;
        int layer = b - 580;
        int f = tid;
        const float* W2p = W2 + layer * 2 * DD * DD;
        float accA = b2[layer * DD + f];
        float accB = 0.f;
#pragma unroll 4
        for (int k = 0; k < DD; k++) {
            accA += b1[layer * DD + k] * W2p[k * DD + f];
            accB += b0[layer * DD + k] * W2p[(DD + k) * DD + f];
        }
        g_biasA[layer * DD + f] = accA;
        g_biasB[layer * DD + f] = accB;
    }
}

// ---------------- HMMA dual GEMM: warp = (mat, nhalf, rowgrp) ----------------
// 256 threads = 8 warps, MT=64. Each warp: 32 rows x 48 cols -> c[6][8];
// 6 B-LDG feed 12 MMA per stage. Both outputs stored fp16 padded.
__global__ __launch_bounds__(256) void tensor_gemm(const float* __restrict__ x32,
                                                   int layer, int N) {
    extern __shared__ __half sm[];
    __half* sA = sm;
    const int tid  = threadIdx.x;
    const int row0 = blockIdx.x * MT;

    // ---- fill A tile (64 rows x 96) fp16 ----
#pragma unroll
    for (int i = 0; i < 6; i++) {           // 64*24 chunks / 256 threads
        int idx = tid + i * 256;
        int m = idx / 24, c4 = idx % 24;
        int k = c4 * 4;
        int row = row0 + m;
        uint2 hv = make_uint2(0u, 0u);
        if (row < N) {
            if (layer == 0) {
                float4 v = ((const float4*)(x32 + (size_t)row * DD))[c4];
                __half2 p0 = __floats2half2_rn(v.x, v.y);
                __half2 p1 = __floats2half2_rn(v.z, v.w);
                hv.x = *(uint32_t*)&p0;
                hv.y = *(uint32_t*)&p1;
            } else {
                hv = *(const uint2*)(g_xh16 + (size_t)row * HS + k);
            }
        }
        *(uint2*)&sA[m * AS + k] = hv;
    }
    __syncthreads();

    const int warp = tid >> 5, lane = tid & 31;
    const int gid = lane >> 2, tig = lane & 3;
    const int mat   = warp >> 2;            // 0 or 1
    const int nhalf = (warp >> 1) & 1;      // ntiles 0..5 or 6..11
    const int rbase = (warp & 1) * 32;      // rows rbase..rbase+31

    float c[6][8];
#pragma unroll
    for (int nt = 0; nt < 6; nt++)
#pragma unroll
        for (int q = 0; q < 8; q++) c[nt][q] = 0.f;

#pragma unroll
    for (int span = 0; span < 2; span++) {  // span0: W_hi, span1: W_lo
#pragma unroll
        for (int kc = 0; kc < 6; kc++) {
            const int k0 = kc * 16 + tig * 2;
            uint32_t a0 = *(const uint32_t*)&sA[(rbase + gid)      * AS + k0];
            uint32_t a1 = *(const uint32_t*)&sA[(rbase + gid + 8)  * AS + k0];
            uint32_t a2 = *(const uint32_t*)&sA[(rbase + gid)      * AS + k0 + 8];
            uint32_t a3 = *(const uint32_t*)&sA[(rbase + gid + 8)  * AS + k0 + 8];
            uint32_t a4 = *(const uint32_t*)&sA[(rbase + gid + 16) * AS + k0];
            uint32_t a5 = *(const uint32_t*)&sA[(rbase + gid + 24) * AS + k0];
            uint32_t a6 = *(const uint32_t*)&sA[(rbase + gid + 16) * AS + k0 + 8];
            uint32_t a7 = *(const uint32_t*)&sA[(rbase + gid + 24) * AS + k0 + 8];
            const uint2* bp = &g_Bfrag[layer][mat][span][kc][nhalf * 6][lane];
#pragma unroll
            for (int nt = 0; nt < 6; nt++) {
                uint2 b = __ldg(&bp[nt * 32]);
                asm volatile(
                    "mma.sync.aligned.m16n8k16.row.col.f32.f16.f16.f32 "
                    "{%0,%1,%2,%3}, {%4,%5,%6,%7}, {%8,%9}, {%0,%1,%2,%3};"
                    : "+f"(c[nt][0]), "+f"(c[nt][1]), "+f"(c[nt][2]), "+f"(c[nt][3])
                    : "r"(a0), "r"(a1), "r"(a2), "r"(a3), "r"(b.x), "r"(b.y));
                asm volatile(
                    "mma.sync.aligned.m16n8k16.row.col.f32.f16.f16.f32 "
                    "{%0,%1,%2,%3}, {%4,%5,%6,%7}, {%8,%9}, {%0,%1,%2,%3};"
                    : "+f"(c[nt][4]), "+f"(c[nt][5]), "+f"(c[nt][6]), "+f"(c[nt][7])
                    : "r"(a4), "r"(a5), "r"(a6), "r"(a7), "r"(b.x), "r"(b.y));
            }
        }
    }

    // ---- epilogue: fp16 stores for both mats ----
    __half* dst = (mat == 0) ? g_y116 : g_h16;
    const int r0 = row0 + rbase + gid;
#pragma unroll
    for (int nt = 0; nt < 6; nt++) {
        int col = (nhalf * 6 + nt) * 8 + tig * 2;
        if (r0 < N)      *(__half2*)&dst[(size_t)r0        * HS + col] = __floats2half2_rn(c[nt][0], c[nt][1]);
        if (r0 + 8 < N)  *(__half2*)&dst[(size_t)(r0 + 8)  * HS + col] = __floats2half2_rn(c[nt][2], c[nt][3]);
        if (r0 + 16 < N) *(__half2*)&dst[(size_t)(r0 + 16) * HS + col] = __floats2half2_rn(c[nt][4], c[nt][5]);
        if (r0 + 24 < N) *(__half2*)&dst[(size_t)(r0 + 24) * HS + col] = __floats2half2_rn(c[nt][6], c[nt][7]);
    }
}

// ---------------- aggregation + bias + unbiased-std normalize ----------------
// One warp per node. Lanes 0-23 own features {4l..4l+3}; one uint2 LDG per edge
// row AND per y1 row (all fp16 padded).
__global__ __launch_bounds__(256) void agg_norm(const int* __restrict__ esrc,
                                                float* __restrict__ outF,
                                                int layer, int mode, int N) {
    int warp = (blockIdx.x * blockDim.x + threadIdx.x) >> 5;
    int lane = threadIdx.x & 31;
    if (warp >= N) return;
    const int node = warp;
    const int beg = g_rowptr[node];
    const int end = g_rowptr[node + 1];
    const bool act = lane < 24;
    const int fb = 4 * lane;           // features fb..fb+3 (lane < 24)

    float a0 = 0.f, a1 = 0.f, a2 = 0.f, a3 = 0.f;
    if (act) {
        const float* bA = g_biasA + layer * DD;
        const float* bB = g_biasB + layer * DD;
        const float deg = (float)(end - beg);
        uint2 yv = *(const uint2*)&g_y116[(size_t)node * HS + fb];
        float2 yp = __half22float2(*(__half2*)&yv.x);
        float2 yq = __half22float2(*(__half2*)&yv.y);
        float4 bA4 = *(const float4*)&bA[fb];
        float4 bB4 = *(const float4*)&bB[fb];
        a0 = yp.x + bA4.x + deg * bB4.x;
        a1 = yp.y + bA4.y + deg * bB4.y;
        a2 = yq.x + bA4.z + deg * bB4.z;
        a3 = yq.y + bA4.w + deg * bB4.w;
    }

    int e = beg;
    for (; e + 16 <= end; e += 16) {
        int sidx[16];
#pragma unroll
        for (int j = 0; j < 16; j++) sidx[j] = __ldg(&esrc[e + j]);
        float t0 = 0.f, t1 = 0.f, t2 = 0.f, t3 = 0.f;
        float u0 = 0.f, u1 = 0.f, u2 = 0.f, u3 = 0.f;
        if (act) {
#pragma unroll
            for (int j = 0; j < 16; j += 2) {
                uint2 v = __ldg((const uint2*)(g_h16 + (size_t)sidx[j] * HS) + lane);
                float2 p = __half22float2(*(__half2*)&v.x);
                float2 q = __half22float2(*(__half2*)&v.y);
                t0 += p.x; t1 += p.y; t2 += q.x; t3 += q.y;
                uint2 w = __ldg((const uint2*)(g_h16 + (size_t)sidx[j + 1] * HS) + lane);
                float2 r = __half22float2(*(__half2*)&w.x);
                float2 s = __half22float2(*(__half2*)&w.y);
                u0 += r.x; u1 += r.y; u2 += s.x; u3 += s.y;
            }
        }
        a0 += t0 + u0; a1 += t1 + u1; a2 += t2 + u2; a3 += t3 + u3;
    }
    for (; e + 4 <= end; e += 4) {
        int sidx[4];
#pragma unroll
        for (int j = 0; j < 4; j++) sidx[j] = __ldg(&esrc[e + j]);
        if (act) {
#pragma unroll
            for (int j = 0; j < 4; j++) {
                uint2 v = __ldg((const uint2*)(g_h16 + (size_t)sidx[j] * HS) + lane);
                float2 p = __half22float2(*(__half2*)&v.x);
                float2 q = __half22float2(*(__half2*)&v.y);
                a0 += p.x; a1 += p.y; a2 += q.x; a3 += q.y;
            }
        }
    }
    for (; e < end; e++) {
        if (act) {
            uint2 v = __ldg((const uint2*)(g_h16 + (size_t)__ldg(&esrc[e]) * HS) + lane);
            float2 p = __half22float2(*(__half2*)&v.x);
            float2 q = __half22float2(*(__half2*)&v.y);
            a0 += p.x; a1 += p.y; a2 += q.x; a3 += q.y;
        }
    }

    float sum = (a0 + a1) + (a2 + a3);
#pragma unroll
    for (int o = 16; o; o >>= 1) sum += __shfl_xor_sync(0xffffffffu, sum, o);
    float mean = sum * (1.0f / 96.0f);
    float d0 = a0 - mean, d1 = a1 - mean, d2 = a2 - mean, d3 = a3 - mean;
    float sq = act ? (d0 * d0 + d1 * d1) + (d2 * d2 + d3 * d3) : 0.f;
#pragma unroll
    for (int o = 16; o; o >>= 1) sq += __shfl_xor_sync(0xffffffffu, sq, o);
    float inv = rsqrtf(sq * (1.0f / 95.0f));

    if (act) {
        float v0 = a0 * inv, v1 = a1 * inv, v2 = a2 * inv, v3 = a3 * inv;
        if (mode == 1) {
            *(float4*)&outF[(size_t)node * DD + fb] = make_float4(v0, v1, v2, v3);
        } else {
            __half2 p0 = __floats2half2_rn(v0, v1);
            __half2 p1 = __floats2half2_rn(v2, v3);
            uint2 pk;
            pk.x = *(uint32_t*)&p0;
            pk.y = *(uint32_t*)&p1;
            *(uint2*)&g_xh16[(size_t)node * HS + fb] = pk;
        }
    }
}

// ---------------- host ----------------
extern "C" void kernel_launch(void* const* d_in, const int* in_sizes, int n_in,
                              void* d_out, int out_size) {
    const float* x   = (const float*)d_in[0];
    const float* W0  = (const float*)d_in[1];
    const float* b0  = (const float*)d_in[2];
    const float* W1  = (const float*)d_in[3];
    const float* b1  = (const float*)d_in[4];
    const float* W2  = (const float*)d_in[5];
    const float* b2  = (const float*)d_in[6];
    const int* esrc  = (const int*)d_in[7];
    const int* edst  = (const int*)d_in[8];
    float* out = (float*)d_out;

    const int N = in_sizes[0] / DD;
    const int E = in_sizes[7];

    const int smem_bytes = MT * AS * (int)sizeof(__half);   // 13312
    cudaFuncSetAttribute(tensor_gemm, cudaFuncAttributeMaxDynamicSharedMemorySize, smem_bytes);

    setup_all<<<582, 256>>>(edst, W0, W1, W2, b0, b1, b2, E, N);

    const int gemm_grid = (N + MT - 1) / MT;
    const int agg_grid  = (N * 32 + 255) / 256;

    // layer 0: x fp32 -> GEMM -> agg_norm writes fp16 x (padded rows)
    tensor_gemm<<<gemm_grid, 256, smem_bytes>>>(x, 0, N);
    agg_norm<<<agg_grid, 256>>>(esrc, nullptr, 0, 0, N);

    // layer 1: fp16 x -> GEMM -> agg_norm writes fp32 out
    tensor_gemm<<<gemm_grid, 256, smem_bytes>>>(nullptr, 1, N);
    agg_norm<<<agg_grid, 256>>>(esrc, out, 1, 1, N);
}

// round 16
// speedup vs baseline: 1.0025x; 1.0025x over previous
#include <cuda_runtime.h>
#include <cuda_bf16.h>
#include <cuda_fp16.h>
#include <cstdint>
#include <math.h>

#define NN 50000
#define EE 800000
#define DD 96
#define HS 128                 // padded row stride (halves) for g_h16 / g_xh16
#define MT 64                  // GEMM tile rows per block
#define AS 104                 // A smem row stride in fp16 elems

// ---------------- scratch (device globals) ----------------
__device__ float g_y1[NN * DD];                 // x @ Wc1 (self path), fp32
__device__ __half g_h16[NN * HS];               // x @ Wc0 (neighbor), fp16, padded rows
__device__ __half g_xh16[NN * HS];              // layer-1 input, fp16, padded rows
__device__ int   g_rowptr[NN + 1];
// B fragments for mma.sync m16n8k16 (row.col), fp16:
// [layer][mat][hl: 0=hi,1=lo][kchunk 0..5][ntile 0..11][lane 0..31] -> {b0,b1}
__device__ uint2 g_Bfrag[2][2][2][6][12][32];
__device__ float g_biasA[2 * DD];               // b1 @ W2_top + b2
__device__ float g_biasB[2 * DD];               // b0 @ W2_bot (x in-degree)

static __device__ __forceinline__ unsigned short h16_bits(__half h) {
    __half_raw r = *(__half_raw*)&h;
    return r.x;
}

// ---------------- fused setup: rowptr + combine_w + combine_b ----------------
__global__ void setup_all(const int* __restrict__ edst,
                          const float* __restrict__ W0,
                          const float* __restrict__ W1,
                          const float* __restrict__ W2,
                          const float* __restrict__ b0,
                          const float* __restrict__ b1,
                          const float* __restrict__ b2,
                          int E, int N) {
    const int b = blockIdx.x;
    const int tid = threadIdx.x;
    if (b < 196) {
        int n = b * 256 + tid;
        if (n > N) return;
        int lo = 0, hi = E;
        while (lo < hi) { int mid = (lo + hi) >> 1; if (edst[mid] < n) lo = mid + 1; else hi = mid; }
        g_rowptr[n] = lo;
    } else if (b < 580) {
        if (tid >= DD) return;
        int id = b - 196;                 // 0..383
        int r = id % DD;                  // k index
        int mat = (id / DD) & 1;
        int layer = id / (2 * DD);
        int f = tid;                      // n index
        const float* Wa  = (mat == 0 ? W1 : W0) + layer * DD * DD + r * DD;
        const float* W2p = W2 + layer * 2 * DD * DD + (mat == 0 ? 0 : DD) * DD;
        float acc = 0.f;
#pragma unroll 4
        for (int k = 0; k < DD; k++) acc += Wa[k] * W2p[k * DD + f];
        __half hi = __float2half_rn(acc);
        __half lo = __float2half_rn(acc - __half2float(hi));
        int kc  = r >> 4, rem = r & 15;
        int tig = (rem >> 1) & 3, jhi = rem >> 3, jlo = rem & 1;
        int us  = jhi * 2 + jlo;
        int nt  = f >> 3, gid = f & 7;
        int lane = gid * 4 + tig;
        unsigned short* ph = (unsigned short*)&g_Bfrag[layer][mat][0][kc][nt][lane];
        unsigned short* pl = (unsigned short*)&g_Bfrag[layer][mat][1][kc][nt][lane];
        ph[us] = h16_bits(hi);
        pl[us] = h16_bits(lo);
    } else {
        if (tid >= DD) return;
        int layer = b - 580;
        int f = tid;
        const float* W2p = W2 + layer * 2 * DD * DD;
        float accA = b2[layer * DD + f];
        float accB = 0.f;
#pragma unroll 4
        for (int k = 0; k < DD; k++) {
            accA += b1[layer * DD + k] * W2p[k * DD + f];
            accB += b0[layer * DD + k] * W2p[(DD + k) * DD + f];
        }
        g_biasA[layer * DD + f] = accA;
        g_biasB[layer * DD + f] = accB;
    }
}

// ---------------- HMMA dual GEMM: warp = (mat, nhalf, rowgrp) ----------------
// 256 threads = 8 warps, MT=64. Each warp: 32 rows x 48 cols -> c[6][8];
// 6 B-LDG feed 12 MMA per stage. (R14 shape — measured best.)
__global__ __launch_bounds__(256) void tensor_gemm(const float* __restrict__ x32,
                                                   int layer, int N) {
    extern __shared__ __half sm[];
    __half* sA = sm;
    const int tid  = threadIdx.x;
    const int row0 = blockIdx.x * MT;

    // ---- fill A tile (64 rows x 96) fp16 ----
#pragma unroll
    for (int i = 0; i < 6; i++) {           // 64*24 chunks / 256 threads
        int idx = tid + i * 256;
        int m = idx / 24, c4 = idx % 24;
        int k = c4 * 4;
        int row = row0 + m;
        uint2 hv = make_uint2(0u, 0u);
        if (row < N) {
            if (layer == 0) {
                float4 v = ((const float4*)(x32 + (size_t)row * DD))[c4];
                __half2 p0 = __floats2half2_rn(v.x, v.y);
                __half2 p1 = __floats2half2_rn(v.z, v.w);
                hv.x = *(uint32_t*)&p0;
                hv.y = *(uint32_t*)&p1;
            } else {
                hv = *(const uint2*)(g_xh16 + (size_t)row * HS + k);
            }
        }
        *(uint2*)&sA[m * AS + k] = hv;
    }
    __syncthreads();

    const int warp = tid >> 5, lane = tid & 31;
    const int gid = lane >> 2, tig = lane & 3;
    const int mat   = warp >> 2;            // 0 or 1
    const int nhalf = (warp >> 1) & 1;      // ntiles 0..5 or 6..11
    const int rbase = (warp & 1) * 32;      // rows rbase..rbase+31

    float c[6][8];
#pragma unroll
    for (int nt = 0; nt < 6; nt++)
#pragma unroll
        for (int q = 0; q < 8; q++) c[nt][q] = 0.f;

#pragma unroll
    for (int span = 0; span < 2; span++) {  // span0: W_hi, span1: W_lo
#pragma unroll
        for (int kc = 0; kc < 6; kc++) {
            const int k0 = kc * 16 + tig * 2;
            uint32_t a0 = *(const uint32_t*)&sA[(rbase + gid)      * AS + k0];
            uint32_t a1 = *(const uint32_t*)&sA[(rbase + gid + 8)  * AS + k0];
            uint32_t a2 = *(const uint32_t*)&sA[(rbase + gid)      * AS + k0 + 8];
            uint32_t a3 = *(const uint32_t*)&sA[(rbase + gid + 8)  * AS + k0 + 8];
            uint32_t a4 = *(const uint32_t*)&sA[(rbase + gid + 16) * AS + k0];
            uint32_t a5 = *(const uint32_t*)&sA[(rbase + gid + 24) * AS + k0];
            uint32_t a6 = *(const uint32_t*)&sA[(rbase + gid + 16) * AS + k0 + 8];
            uint32_t a7 = *(const uint32_t*)&sA[(rbase + gid + 24) * AS + k0 + 8];
            const uint2* bp = &g_Bfrag[layer][mat][span][kc][nhalf * 6][lane];
#pragma unroll
            for (int nt = 0; nt < 6; nt++) {
                uint2 b = __ldg(&bp[nt * 32]);
                asm volatile(
                    "mma.sync.aligned.m16n8k16.row.col.f32.f16.f16.f32 "
                    "{%0,%1,%2,%3}, {%4,%5,%6,%7}, {%8,%9}, {%0,%1,%2,%3};"
                    : "+f"(c[nt][0]), "+f"(c[nt][1]), "+f"(c[nt][2]), "+f"(c[nt][3])
                    : "r"(a0), "r"(a1), "r"(a2), "r"(a3), "r"(b.x), "r"(b.y));
                asm volatile(
                    "mma.sync.aligned.m16n8k16.row.col.f32.f16.f16.f32 "
                    "{%0,%1,%2,%3}, {%4,%5,%6,%7}, {%8,%9}, {%0,%1,%2,%3};"
                    : "+f"(c[nt][4]), "+f"(c[nt][5]), "+f"(c[nt][6]), "+f"(c[nt][7])
                    : "r"(a4), "r"(a5), "r"(a6), "r"(a7), "r"(b.x), "r"(b.y));
            }
        }
    }

    // ---- epilogue: 4 row-subgroups x 6 ntiles ----
    const int r0 = row0 + rbase + gid;
    if (mat == 0) {
#pragma unroll
        for (int nt = 0; nt < 6; nt++) {
            int col = (nhalf * 6 + nt) * 8 + tig * 2;
            if (r0 < N)      *(float2*)&g_y1[(size_t)r0        * DD + col] = make_float2(c[nt][0], c[nt][1]);
            if (r0 + 8 < N)  *(float2*)&g_y1[(size_t)(r0 + 8)  * DD + col] = make_float2(c[nt][2], c[nt][3]);
            if (r0 + 16 < N) *(float2*)&g_y1[(size_t)(r0 + 16) * DD + col] = make_float2(c[nt][4], c[nt][5]);
            if (r0 + 24 < N) *(float2*)&g_y1[(size_t)(r0 + 24) * DD + col] = make_float2(c[nt][6], c[nt][7]);
        }
    } else {
#pragma unroll
        for (int nt = 0; nt < 6; nt++) {
            int col = (nhalf * 6 + nt) * 8 + tig * 2;
            if (r0 < N)      *(__half2*)&g_h16[(size_t)r0        * HS + col] = __floats2half2_rn(c[nt][0], c[nt][1]);
            if (r0 + 8 < N)  *(__half2*)&g_h16[(size_t)(r0 + 8)  * HS + col] = __floats2half2_rn(c[nt][2], c[nt][3]);
            if (r0 + 16 < N) *(__half2*)&g_h16[(size_t)(r0 + 16) * HS + col] = __floats2half2_rn(c[nt][4], c[nt][5]);
            if (r0 + 24 < N) *(__half2*)&g_h16[(size_t)(r0 + 24) * HS + col] = __floats2half2_rn(c[nt][6], c[nt][7]);
        }
    }
}

// ---------------- aggregation + bias + unbiased-std normalize ----------------
// One warp per node. Lanes 0-23 own features {4l..4l+3}; one uint2 LDG per edge.
// Edge indices loaded as uniform int4 (4 LSU issues per 16 edges instead of 16).
__global__ __launch_bounds__(256) void agg_norm(const int* __restrict__ esrc,
                                                float* __restrict__ outF,
                                                int layer, int mode, int N) {
    int warp = (blockIdx.x * blockDim.x + threadIdx.x) >> 5;
    int lane = threadIdx.x & 31;
    if (warp >= N) return;
    const int node = warp;
    const int beg = g_rowptr[node];
    const int end = g_rowptr[node + 1];
    const bool act = lane < 24;
    const int fb = 4 * lane;           // features fb..fb+3 (lane < 24)

    float a0 = 0.f, a1 = 0.f, a2 = 0.f, a3 = 0.f;
    if (act) {
        const float* bA = g_biasA + layer * DD;
        const float* bB = g_biasB + layer * DD;
        const float deg = (float)(end - beg);
        float4 y4 = *(const float4*)&g_y1[(size_t)node * DD + fb];
        float4 bA4 = *(const float4*)&bA[fb];
        float4 bB4 = *(const float4*)&bB[fb];
        a0 = y4.x + bA4.x + deg * bB4.x;
        a1 = y4.y + bA4.y + deg * bB4.y;
        a2 = y4.z + bA4.z + deg * bB4.z;
        a3 = y4.w + bA4.w + deg * bB4.w;
    }

    int e = beg;
    // peel to int4 alignment
    for (; e < end && (e & 3); e++) {
        if (act) {
            uint2 v = __ldg((const uint2*)(g_h16 + (size_t)__ldg(&esrc[e]) * HS) + lane);
            float2 p = __half22float2(*(__half2*)&v.x);
            float2 q = __half22float2(*(__half2*)&v.y);
            a0 += p.x; a1 += p.y; a2 += q.x; a3 += q.y;
        }
    }
    // main loop: 16 edges per iter, indices via 4 uniform int4 loads
    for (; e + 16 <= end; e += 16) {
        int4 i4[4];
#pragma unroll
        for (int j = 0; j < 4; j++) i4[j] = __ldg((const int4*)(esrc + e) + j);
        int sidx[16] = { i4[0].x, i4[0].y, i4[0].z, i4[0].w,
                         i4[1].x, i4[1].y, i4[1].z, i4[1].w,
                         i4[2].x, i4[2].y, i4[2].z, i4[2].w,
                         i4[3].x, i4[3].y, i4[3].z, i4[3].w };
        float t0 = 0.f, t1 = 0.f, t2 = 0.f, t3 = 0.f;
        float u0 = 0.f, u1 = 0.f, u2 = 0.f, u3 = 0.f;
        if (act) {
#pragma unroll
            for (int j = 0; j < 16; j += 2) {
                uint2 v = __ldg((const uint2*)(g_h16 + (size_t)sidx[j] * HS) + lane);
                float2 p = __half22float2(*(__half2*)&v.x);
                float2 q = __half22float2(*(__half2*)&v.y);
                t0 += p.x; t1 += p.y; t2 += q.x; t3 += q.y;
                uint2 w = __ldg((const uint2*)(g_h16 + (size_t)sidx[j + 1] * HS) + lane);
                float2 r = __half22float2(*(__half2*)&w.x);
                float2 s = __half22float2(*(__half2*)&w.y);
                u0 += r.x; u1 += r.y; u2 += s.x; u3 += s.y;
            }
        }
        a0 += t0 + u0; a1 += t1 + u1; a2 += t2 + u2; a3 += t3 + u3;
    }
    // 4-edge tail batches (aligned)
    for (; e + 4 <= end; e += 4) {
        int4 i4 = __ldg((const int4*)(esrc + e));
        int sidx[4] = { i4.x, i4.y, i4.z, i4.w };
        if (act) {
#pragma unroll
            for (int j = 0; j < 4; j++) {
                uint2 v = __ldg((const uint2*)(g_h16 + (size_t)sidx[j] * HS) + lane);
                float2 p = __half22float2(*(__half2*)&v.x);
                float2 q = __half22float2(*(__half2*)&v.y);
                a0 += p.x; a1 += p.y; a2 += q.x; a3 += q.y;
            }
        }
    }
    for (; e < end; e++) {
        if (act) {
            uint2 v = __ldg((const uint2*)(g_h16 + (size_t)__ldg(&esrc[e]) * HS) + lane);
            float2 p = __half22float2(*(__half2*)&v.x);
            float2 q = __half22float2(*(__half2*)&v.y);
            a0 += p.x; a1 += p.y; a2 += q.x; a3 += q.y;
        }
    }

    float sum = (a0 + a1) + (a2 + a3);
#pragma unroll
    for (int o = 16; o; o >>= 1) sum += __shfl_xor_sync(0xffffffffu, sum, o);
    float mean = sum * (1.0f / 96.0f);
    float d0 = a0 - mean, d1 = a1 - mean, d2 = a2 - mean, d3 = a3 - mean;
    float sq = act ? (d0 * d0 + d1 * d1) + (d2 * d2 + d3 * d3) : 0.f;
#pragma unroll
    for (int o = 16; o; o >>= 1) sq += __shfl_xor_sync(0xffffffffu, sq, o);
    float inv = rsqrtf(sq * (1.0f / 95.0f));

    if (act) {
        float v0 = a0 * inv, v1 = a1 * inv, v2 = a2 * inv, v3 = a3 * inv;
        if (mode == 1) {
            *(float4*)&outF[(size_t)node * DD + fb] = make_float4(v0, v1, v2, v3);
        } else {
            __half2 p0 = __floats2half2_rn(v0, v1);
            __half2 p1 = __floats2half2_rn(v2, v3);
            uint2 pk;
            pk.x = *(uint32_t*)&p0;
            pk.y = *(uint32_t*)&p1;
            *(uint2*)&g_xh16[(size_t)node * HS + fb] = pk;
        }
    }
}

// ---------------- host ----------------
extern "C" void kernel_launch(void* const* d_in, const int* in_sizes, int n_in,
                              void* d_out, int out_size) {
    const float* x   = (const float*)d_in[0];
    const float* W0  = (const float*)d_in[1];
    const float* b0  = (const float*)d_in[2];
    const float* W1  = (const float*)d_in[3];
    const float* b1  = (const float*)d_in[4];
    const float* W2  = (const float*)d_in[5];
    const float* b2  = (const float*)d_in[6];
    const int* esrc  = (const int*)d_in[7];
    const int* edst  = (const int*)d_in[8];
    float* out = (float*)d_out;

    const int N = in_sizes[0] / DD;
    const int E = in_sizes[7];

    const int smem_bytes = MT * AS * (int)sizeof(__half);   // 13312
    cudaFuncSetAttribute(tensor_gemm, cudaFuncAttributeMaxDynamicSharedMemorySize, smem_bytes);

    setup_all<<<582, 256>>>(edst, W0, W1, W2, b0, b1, b2, E, N);

    const int gemm_grid = (N + MT - 1) / MT;
    const int agg_grid  = (N * 32 + 255) / 256;

    // layer 0: x fp32 -> GEMM -> agg_norm writes fp16 x (padded rows)
    tensor_gemm<<<gemm_grid, 256, smem_bytes>>>(x, 0, N);
    agg_norm<<<agg_grid, 256>>>(esrc, nullptr, 0, 0, N);

    // layer 1: fp16 x -> GEMM -> agg_norm writes fp32 out
    tensor_gemm<<<gemm_grid, 256, smem_bytes>>>(nullptr, 1, N);
    agg_norm<<<agg_grid, 256>>>(esrc, out, 1, 1, N);
}

// round 17
// speedup vs baseline: 1.1445x; 1.1417x over previous
#include <cuda_runtime.h>
#include <cuda_bf16.h>
#include <cuda_fp16.h>
#include <cstdint>
#include <math.h>

#define NN 50000
#define EE 800000
#define DD 96
#define HS 128                 // padded row stride (halves) for g_h16 / g_xh16
#define MT 64                  // GEMM tile rows per block
#define AS 104                 // A smem row stride in fp16 elems

// ---------------- scratch (device globals) ----------------
__device__ float g_y1[NN * DD];                 // x @ Wc1 (self path), fp32
__device__ __half g_h16[NN * HS];               // x @ Wc0 (neighbor), fp16, padded rows
__device__ __half g_xh16[NN * HS];              // layer-1 input, fp16, padded rows
__device__ int   g_rowptr[NN + 1];
// B fragments for mma.sync m16n8k16 (row.col), fp16 (single term):
// [layer][mat][kchunk 0..5][ntile 0..11][lane 0..31] -> {b0,b1}
__device__ uint2 g_Bfrag[2][2][6][12][32];
__device__ float g_biasA[2 * DD];               // b1 @ W2_top + b2
__device__ float g_biasB[2 * DD];               // b0 @ W2_bot (x in-degree)

static __device__ __forceinline__ unsigned short h16_bits(__half h) {
    __half_raw r = *(__half_raw*)&h;
    return r.x;
}

// ---------------- fused setup: rowptr + combine_w + combine_b ----------------
__global__ void setup_all(const int* __restrict__ edst,
                          const float* __restrict__ W0,
                          const float* __restrict__ W1,
                          const float* __restrict__ W2,
                          const float* __restrict__ b0,
                          const float* __restrict__ b1,
                          const float* __restrict__ b2,
                          int E, int N) {
    const int b = blockIdx.x;
    const int tid = threadIdx.x;
    if (b < 196) {
        int n = b * 256 + tid;
        if (n > N) return;
        int lo = 0, hi = E;
        while (lo < hi) { int mid = (lo + hi) >> 1; if (edst[mid] < n) lo = mid + 1; else hi = mid; }
        g_rowptr[n] = lo;
    } else if (b < 580) {
        if (tid >= DD) return;
        int id = b - 196;                 // 0..383
        int r = id % DD;                  // k index
        int mat = (id / DD) & 1;
        int layer = id / (2 * DD);
        int f = tid;                      // n index
        const float* Wa  = (mat == 0 ? W1 : W0) + layer * DD * DD + r * DD;
        const float* W2p = W2 + layer * 2 * DD * DD + (mat == 0 ? 0 : DD) * DD;
        float acc = 0.f;
#pragma unroll 4
        for (int k = 0; k < DD; k++) acc += Wa[k] * W2p[k * DD + f];
        __half hi = __float2half_rn(acc);
        int kc  = r >> 4, rem = r & 15;
        int tig = (rem >> 1) & 3, jhi = rem >> 3, jlo = rem & 1;
        int us  = jhi * 2 + jlo;           // ushort slot 0..3 within uint2
        int nt  = f >> 3, gid = f & 7;
        int lane = gid * 4 + tig;
        unsigned short* ph = (unsigned short*)&g_Bfrag[layer][mat][kc][nt][lane];
        ph[us] = h16_bits(hi);
    } else {
        if (tid >= DD) return;
        int layer = b - 580;
        int f = tid;
        const float* W2p = W2 + layer * 2 * DD * DD;
        float accA = b2[layer * DD + f];
        float accB = 0.f;
#pragma unroll 4
        for (int k = 0; k < DD; k++) {
            accA += b1[layer * DD + k] * W2p[k * DD + f];
            accB += b0[layer * DD + k] * W2p[(DD + k) * DD + f];
        }
        g_biasA[layer * DD + f] = accA;
        g_biasB[layer * DD + f] = accB;
    }
}

// ---------------- HMMA dual GEMM: warp = (mat, nhalf, rowgrp) ----------------
// 256 threads = 8 warps, MT=64. Each warp: 32 rows x 48 cols -> c[6][8];
// 6 B-LDG feed 12 MMA per stage; SINGLE span (plain fp16 weights), 6 stages.
__global__ __launch_bounds__(256) void tensor_gemm(const float* __restrict__ x32,
                                                   int layer, int N) {
    extern __shared__ __half sm[];
    __half* sA = sm;
    const int tid  = threadIdx.x;
    const int row0 = blockIdx.x * MT;

    // ---- fill A tile (64 rows x 96) fp16 ----
#pragma unroll
    for (int i = 0; i < 6; i++) {           // 64*24 chunks / 256 threads
        int idx = tid + i * 256;
        int m = idx / 24, c4 = idx % 24;
        int k = c4 * 4;
        int row = row0 + m;
        uint2 hv = make_uint2(0u, 0u);
        if (row < N) {
            if (layer == 0) {
                float4 v = ((const float4*)(x32 + (size_t)row * DD))[c4];
                __half2 p0 = __floats2half2_rn(v.x, v.y);
                __half2 p1 = __floats2half2_rn(v.z, v.w);
                hv.x = *(uint32_t*)&p0;
                hv.y = *(uint32_t*)&p1;
            } else {
                hv = *(const uint2*)(g_xh16 + (size_t)row * HS + k);
            }
        }
        *(uint2*)&sA[m * AS + k] = hv;
    }
    __syncthreads();

    const int warp = tid >> 5, lane = tid & 31;
    const int gid = lane >> 2, tig = lane & 3;
    const int mat   = warp >> 2;            // 0 or 1
    const int nhalf = (warp >> 1) & 1;      // ntiles 0..5 or 6..11
    const int rbase = (warp & 1) * 32;      // rows rbase..rbase+31

    float c[6][8];
#pragma unroll
    for (int nt = 0; nt < 6; nt++)
#pragma unroll
        for (int q = 0; q < 8; q++) c[nt][q] = 0.f;

#pragma unroll
    for (int kc = 0; kc < 6; kc++) {
        const int k0 = kc * 16 + tig * 2;
        uint32_t a0 = *(const uint32_t*)&sA[(rbase + gid)      * AS + k0];
        uint32_t a1 = *(const uint32_t*)&sA[(rbase + gid + 8)  * AS + k0];
        uint32_t a2 = *(const uint32_t*)&sA[(rbase + gid)      * AS + k0 + 8];
        uint32_t a3 = *(const uint32_t*)&sA[(rbase + gid + 8)  * AS + k0 + 8];
        uint32_t a4 = *(const uint32_t*)&sA[(rbase + gid + 16) * AS + k0];
        uint32_t a5 = *(const uint32_t*)&sA[(rbase + gid + 24) * AS + k0];
        uint32_t a6 = *(const uint32_t*)&sA[(rbase + gid + 16) * AS + k0 + 8];
        uint32_t a7 = *(const uint32_t*)&sA[(rbase + gid + 24) * AS + k0 + 8];
        const uint2* bp = &g_Bfrag[layer][mat][kc][nhalf * 6][lane];
#pragma unroll
        for (int nt = 0; nt < 6; nt++) {
            uint2 b = __ldg(&bp[nt * 32]);
            asm volatile(
                "mma.sync.aligned.m16n8k16.row.col.f32.f16.f16.f32 "
                "{%0,%1,%2,%3}, {%4,%5,%6,%7}, {%8,%9}, {%0,%1,%2,%3};"
                : "+f"(c[nt][0]), "+f"(c[nt][1]), "+f"(c[nt][2]), "+f"(c[nt][3])
                : "r"(a0), "r"(a1), "r"(a2), "r"(a3), "r"(b.x), "r"(b.y));
            asm volatile(
                "mma.sync.aligned.m16n8k16.row.col.f32.f16.f16.f32 "
                "{%0,%1,%2,%3}, {%4,%5,%6,%7}, {%8,%9}, {%0,%1,%2,%3};"
                : "+f"(c[nt][4]), "+f"(c[nt][5]), "+f"(c[nt][6]), "+f"(c[nt][7])
                : "r"(a4), "r"(a5), "r"(a6), "r"(a7), "r"(b.x), "r"(b.y));
        }
    }

    // ---- epilogue: 4 row-subgroups x 6 ntiles ----
    const int r0 = row0 + rbase + gid;
    if (mat == 0) {
#pragma unroll
        for (int nt = 0; nt < 6; nt++) {
            int col = (nhalf * 6 + nt) * 8 + tig * 2;
            if (r0 < N)      *(float2*)&g_y1[(size_t)r0        * DD + col] = make_float2(c[nt][0], c[nt][1]);
            if (r0 + 8 < N)  *(float2*)&g_y1[(size_t)(r0 + 8)  * DD + col] = make_float2(c[nt][2], c[nt][3]);
            if (r0 + 16 < N) *(float2*)&g_y1[(size_t)(r0 + 16) * DD + col] = make_float2(c[nt][4], c[nt][5]);
            if (r0 + 24 < N) *(float2*)&g_y1[(size_t)(r0 + 24) * DD + col] = make_float2(c[nt][6], c[nt][7]);
        }
    } else {
#pragma unroll
        for (int nt = 0; nt < 6; nt++) {
            int col = (nhalf * 6 + nt) * 8 + tig * 2;
            if (r0 < N)      *(__half2*)&g_h16[(size_t)r0        * HS + col] = __floats2half2_rn(c[nt][0], c[nt][1]);
            if (r0 + 8 < N)  *(__half2*)&g_h16[(size_t)(r0 + 8)  * HS + col] = __floats2half2_rn(c[nt][2], c[nt][3]);
            if (r0 + 16 < N) *(__half2*)&g_h16[(size_t)(r0 + 16) * HS + col] = __floats2half2_rn(c[nt][4], c[nt][5]);
            if (r0 + 24 < N) *(__half2*)&g_h16[(size_t)(r0 + 24) * HS + col] = __floats2half2_rn(c[nt][6], c[nt][7]);
        }
    }
}

// ---------------- aggregation + bias + unbiased-std normalize ----------------
// One warp per node (R14 shape — measured best). Lanes 0-23 own features
// {4l..4l+3}; one uint2 LDG per edge; 16 outstanding gathers per batch.
__global__ __launch_bounds__(256) void agg_norm(const int* __restrict__ esrc,
                                                float* __restrict__ outF,
                                                int layer, int mode, int N) {
    int warp = (blockIdx.x * blockDim.x + threadIdx.x) >> 5;
    int lane = threadIdx.x & 31;
    if (warp >= N) return;
    const int node = warp;
    const int beg = g_rowptr[node];
    const int end = g_rowptr[node + 1];
    const bool act = lane < 24;
    const int fb = 4 * lane;           // features fb..fb+3 (lane < 24)

    float a0 = 0.f, a1 = 0.f, a2 = 0.f, a3 = 0.f;
    if (act) {
        const float* bA = g_biasA + layer * DD;
        const float* bB = g_biasB + layer * DD;
        const float deg = (float)(end - beg);
        float4 y4 = *(const float4*)&g_y1[(size_t)node * DD + fb];
        float4 bA4 = *(const float4*)&bA[fb];
        float4 bB4 = *(const float4*)&bB[fb];
        a0 = y4.x + bA4.x + deg * bB4.x;
        a1 = y4.y + bA4.y + deg * bB4.y;
        a2 = y4.z + bA4.z + deg * bB4.z;
        a3 = y4.w + bA4.w + deg * bB4.w;
    }

    int e = beg;
    for (; e + 16 <= end; e += 16) {
        int sidx[16];
#pragma unroll
        for (int j = 0; j < 16; j++) sidx[j] = __ldg(&esrc[e + j]);
        float t0 = 0.f, t1 = 0.f, t2 = 0.f, t3 = 0.f;
        float u0 = 0.f, u1 = 0.f, u2 = 0.f, u3 = 0.f;
        if (act) {
#pragma unroll
            for (int j = 0; j < 16; j += 2) {
                uint2 v = __ldg((const uint2*)(g_h16 + (size_t)sidx[j] * HS) + lane);
                float2 p = __half22float2(*(__half2*)&v.x);
                float2 q = __half22float2(*(__half2*)&v.y);
                t0 += p.x; t1 += p.y; t2 += q.x; t3 += q.y;
                uint2 w = __ldg((const uint2*)(g_h16 + (size_t)sidx[j + 1] * HS) + lane);
                float2 r = __half22float2(*(__half2*)&w.x);
                float2 s = __half22float2(*(__half2*)&w.y);
                u0 += r.x; u1 += r.y; u2 += s.x; u3 += s.y;
            }
        }
        a0 += t0 + u0; a1 += t1 + u1; a2 += t2 + u2; a3 += t3 + u3;
    }
    for (; e + 4 <= end; e += 4) {
        int sidx[4];
#pragma unroll
        for (int j = 0; j < 4; j++) sidx[j] = __ldg(&esrc[e + j]);
        if (act) {
#pragma unroll
            for (int j = 0; j < 4; j++) {
                uint2 v = __ldg((const uint2*)(g_h16 + (size_t)sidx[j] * HS) + lane);
                float2 p = __half22float2(*(__half2*)&v.x);
                float2 q = __half22float2(*(__half2*)&v.y);
                a0 += p.x; a1 += p.y; a2 += q.x; a3 += q.y;
            }
        }
    }
    for (; e < end; e++) {
        if (act) {
            uint2 v = __ldg((const uint2*)(g_h16 + (size_t)__ldg(&esrc[e]) * HS) + lane);
            float2 p = __half22float2(*(__half2*)&v.x);
            float2 q = __half22float2(*(__half2*)&v.y);
            a0 += p.x; a1 += p.y; a2 += q.x; a3 += q.y;
        }
    }

    float sum = (a0 + a1) + (a2 + a3);
#pragma unroll
    for (int o = 16; o; o >>= 1) sum += __shfl_xor_sync(0xffffffffu, sum, o);
    float mean = sum * (1.0f / 96.0f);
    float d0 = a0 - mean, d1 = a1 - mean, d2 = a2 - mean, d3 = a3 - mean;
    float sq = act ? (d0 * d0 + d1 * d1) + (d2 * d2 + d3 * d3) : 0.f;
#pragma unroll
    for (int o = 16; o; o >>= 1) sq += __shfl_xor_sync(0xffffffffu, sq, o);
    float inv = rsqrtf(sq * (1.0f / 95.0f));

    if (act) {
        float v0 = a0 * inv, v1 = a1 * inv, v2 = a2 * inv, v3 = a3 * inv;
        if (mode == 1) {
            *(float4*)&outF[(size_t)node * DD + fb] = make_float4(v0, v1, v2, v3);
        } else {
            __half2 p0 = __floats2half2_rn(v0, v1);
            __half2 p1 = __floats2half2_rn(v2, v3);
            uint2 pk;
            pk.x = *(uint32_t*)&p0;
            pk.y = *(uint32_t*)&p1;
            *(uint2*)&g_xh16[(size_t)node * HS + fb] = pk;
        }
    }
}

// ---------------- host ----------------
extern "C" void kernel_launch(void* const* d_in, const int* in_sizes, int n_in,
                              void* d_out, int out_size) {
    const float* x   = (const float*)d_in[0];
    const float* W0  = (const float*)d_in[1];
    const float* b0  = (const float*)d_in[2];
    const float* W1  = (const float*)d_in[3];
    const float* b1  = (const float*)d_in[4];
    const float* W2  = (const float*)d_in[5];
    const float* b2  = (const float*)d_in[6];
    const int* esrc  = (const int*)d_in[7];
    const int* edst  = (const int*)d_in[8];
    float* out = (float*)d_out;

    const int N = in_sizes[0] / DD;
    const int E = in_sizes[7];

    const int smem_bytes = MT * AS * (int)sizeof(__half);   // 13312
    cudaFuncSetAttribute(tensor_gemm, cudaFuncAttributeMaxDynamicSharedMemorySize, smem_bytes);

    setup_all<<<582, 256>>>(edst, W0, W1, W2, b0, b1, b2, E, N);

    const int gemm_grid = (N + MT - 1) / MT;
    const int agg_grid  = (N * 32 + 255) / 256;

    // layer 0: x fp32 -> GEMM -> agg_norm writes fp16 x (padded rows)
    tensor_gemm<<<gemm_grid, 256, smem_bytes>>>(x, 0, N);
    agg_norm<<<agg_grid, 256>>>(esrc, nullptr, 0, 0, N);

    // layer 1: fp16 x -> GEMM -> agg_norm writes fp32 out
    tensor_gemm<<<gemm_grid, 256, smem_bytes>>>(nullptr, 1, N);
    agg_norm<<<agg_grid, 256>>>(esrc, out, 1, 1, N);
}